// round 2
// baseline (speedup 1.0000x reference)
#include <cuda_runtime.h>

// Problem: SmallRNNModel — 2-layer tanh RNN, B=64, T=512, I=256, H=512, O=256.
// Round 1: all-fp32 baseline. Structure:
//   K1 pre_gemm:  pre0[t,b,h] = x[b,t,:]@W_ih0^T + b_ih0 + b_hh0        (GEMM 32768x512x256)
//   K2 rnn_rec:   h = tanh(pre0_t + h@W_hh0^T), 512 steps, writes ys0   (persistent, grid barrier)
//   K3 pre_gemm:  pre1 = ys0@W_ih1^T + b_ih1 + b_hh1                    (GEMM 32768x512x512)
//   K4 rnn_rec:   h = tanh(pre1_t + h@W_hh1^T), 512 steps (final h kept as hT)
//   K5 fc:        out[b,o] = hT(:,b)·W_fc[o,:] + b_fc[o]

#define T_STEPS 512
#define BATCH   64
#define HID     512
#define REC_CTAS 128   // 8 n-tiles x 16 k-slices
#define KSPLIT   16

// ---------------- static device scratch (no dynamic allocation allowed) ----
__device__ float g_pre[T_STEPS * BATCH * HID];      // 64 MB, reused for pre0 and pre1
__device__ float g_ys[T_STEPS * BATCH * HID];       // 64 MB, layer-0 outputs [t][b][h]
__device__ float g_partial[KSPLIT * BATCH * HID];   // 2 MB, per-step K-split partials
__device__ float g_hT[HID * BATCH];                 // 128 KB, hidden state transposed [h][b]
__device__ unsigned g_bar_count = 0;
__device__ volatile unsigned g_bar_gen = 0;

// ---------------- software grid barrier (all REC_CTAS co-resident) ---------
__device__ __forceinline__ void grid_barrier() {
    __syncthreads();
    if (threadIdx.x == 0) {
        __threadfence();
        unsigned gen = g_bar_gen;
        if (atomicAdd(&g_bar_count, 1u) == REC_CTAS - 1) {
            atomicExch(&g_bar_count, 0u);
            __threadfence();
            g_bar_gen = gen + 1u;
        } else {
            while (g_bar_gen == gen) { }
            __threadfence();
        }
    }
    __syncthreads();
}

// ---------------- input-projection GEMM ------------------------------------
// out = g_pre[r][n] = sum_k A[r][k] * W[n][k] + b1[n] + b2[n]
// r = t*64 + b  (t-major rows).  M = 32768, N = 512, K = 256 or 512.
// x_layout==1: A row r lives at x + (b*512 + t)*256  (x is [B][T][I])
// x_layout==0: A = g_ys, row r contiguous at r*512.
__global__ void __launch_bounds__(256)
pre_gemm_kernel(const float* __restrict__ Aparam,
                const float* __restrict__ W,
                const float* __restrict__ b1,
                const float* __restrict__ b2,
                int K, int x_layout)
{
    __shared__ float As[16][68];   // [k][m], padded (272B rows keep 16B alignment)
    __shared__ float Bs[16][68];   // [k][n]

    const int tid = threadIdx.x;
    const int nt  = blockIdx.x;    // 0..7
    const int mt  = blockIdx.y;    // 0..511
    const int m0  = (tid >> 4) << 2;   // 0..60
    const int n0  = (tid & 15) << 2;   // 0..60

    const int lm = tid >> 2;           // 0..63 (row loaded by this thread)
    const int lk = (tid & 3) << 2;     // 0,4,8,12

    const float* A = x_layout ? Aparam : g_ys;
    // A row base for row r = mt*64 + lm; in x layout: b = lm, t = mt.
    int arow;
    if (x_layout) arow = (lm * 512 + mt) * 256;
    else          arow = (mt * 64 + lm) * K;
    const float* wrow = W + (nt * 64 + lm) * K;

    float acc[4][4] = {};

    for (int k0 = 0; k0 < K; k0 += 16) {
        float4 av = *(const float4*)(A + arow + k0 + lk);
        float4 wv = *(const float4*)(wrow + k0 + lk);
        As[lk + 0][lm] = av.x; As[lk + 1][lm] = av.y;
        As[lk + 2][lm] = av.z; As[lk + 3][lm] = av.w;
        Bs[lk + 0][lm] = wv.x; Bs[lk + 1][lm] = wv.y;
        Bs[lk + 2][lm] = wv.z; Bs[lk + 3][lm] = wv.w;
        __syncthreads();
        #pragma unroll
        for (int kk = 0; kk < 16; kk++) {
            float4 a = *(const float4*)&As[kk][m0];
            float4 w = *(const float4*)&Bs[kk][n0];
            float av4[4] = {a.x, a.y, a.z, a.w};
            float wv4[4] = {w.x, w.y, w.z, w.w};
            #pragma unroll
            for (int i = 0; i < 4; i++)
                #pragma unroll
                for (int j = 0; j < 4; j++)
                    acc[i][j] += av4[i] * wv4[j];
        }
        __syncthreads();
    }

    const int nbase = nt * 64 + n0;
    float bs[4];
    #pragma unroll
    for (int j = 0; j < 4; j++) bs[j] = b1[nbase + j] + b2[nbase + j];
    #pragma unroll
    for (int i = 0; i < 4; i++) {
        float4 o = make_float4(acc[i][0] + bs[0], acc[i][1] + bs[1],
                               acc[i][2] + bs[2], acc[i][3] + bs[3]);
        *(float4*)&g_pre[(mt * 64 + m0 + i) * 512 + nbase] = o;
    }
}

// ---------------- persistent recurrence kernel -----------------------------
// 128 CTAs: cta = ks*8 + nt.  CTA holds W_hh[nt*64 .. +64][ks*32 .. +32] in smem.
// Per step t:
//   P1: partial[ks][b][n] = sum_{k in slice} hT[k][b] * W[n][k]   (64x64 out, K=32)
//   BAR
//   P2: 1 output/thread: s = pre[t] + sum_ks partial; v=tanh(s);
//       write ys0[t] (layer0 only) and hT[n][b]
//   BAR
__global__ void __launch_bounds__(256)
rnn_rec_kernel(const float* __restrict__ W_hh, int write_ys)
{
    __shared__ float Wst[32][64];   // [k][n]
    __shared__ float hst[32][64];   // [k][b]

    const int tid = threadIdx.x;
    const int cta = blockIdx.x;
    const int nt  = cta & 7;
    const int ks  = cta >> 3;
    const int b0  = (tid >> 4) << 2;
    const int n0  = (tid & 15) << 2;

    // load W slice (once)
    #pragma unroll
    for (int j = 0; j < 8; j++) {
        int e = tid * 8 + j;          // 0..2047
        int n = e >> 5;
        int k = e & 31;
        Wst[k][n] = W_hh[(nt * 64 + n) * 512 + ks * 32 + k];
    }
    // zero initial hidden state
    g_hT[cta * 256 + tid] = 0.0f;
    grid_barrier();

    for (int t = 0; t < T_STEPS; t++) {
        // load this CTA's h slice: hT rows [ks*32, ks*32+32), contiguous 2048 floats
        {
            const float4* src = (const float4*)(g_hT + ks * 2048);
            float4* dst = (float4*)(&hst[0][0]);
            dst[tid]       = src[tid];
            dst[tid + 256] = src[tid + 256];
        }
        __syncthreads();

        float acc[4][4] = {};
        #pragma unroll
        for (int kk = 0; kk < 32; kk++) {
            float4 a = *(const float4*)&hst[kk][b0];
            float4 w = *(const float4*)&Wst[kk][n0];
            float av4[4] = {a.x, a.y, a.z, a.w};
            float wv4[4] = {w.x, w.y, w.z, w.w};
            #pragma unroll
            for (int i = 0; i < 4; i++)
                #pragma unroll
                for (int j = 0; j < 4; j++)
                    acc[i][j] += av4[i] * wv4[j];
        }
        #pragma unroll
        for (int i = 0; i < 4; i++) {
            float4 v = make_float4(acc[i][0], acc[i][1], acc[i][2], acc[i][3]);
            *(float4*)&g_partial[(ks * 64 + b0 + i) * 512 + nt * 64 + n0] = v;
        }
        grid_barrier();

        // P2: reduce + tanh + scatter
        {
            int idx = cta * 256 + tid;          // = b*512 + n, covers all 32768
            float s = g_pre[t * 32768 + idx];
            #pragma unroll
            for (int j = 0; j < KSPLIT; j++)
                s += g_partial[j * 32768 + idx];
            float v = tanhf(s);
            if (write_ys) g_ys[t * 32768 + idx] = v;
            g_hT[(idx & 511) * 64 + (idx >> 9)] = v;
        }
        grid_barrier();
    }
}

// ---------------- final FC --------------------------------------------------
// out[b][o] = sum_h hT[h][b] * W_fc[o][h] + b_fc[o]
__global__ void __launch_bounds__(256)
fc_kernel(const float* __restrict__ Wfc, const float* __restrict__ bfc,
          float* __restrict__ out)
{
    int idx = blockIdx.x * 256 + threadIdx.x;   // 0..16383
    int o = idx >> 6;      // same o across 64 consecutive threads -> W broadcast
    int b = idx & 63;      // consecutive b -> coalesced hT reads
    const float* wr = Wfc + o * 512;
    float s = bfc[o];
    #pragma unroll 8
    for (int h = 0; h < 512; h++)
        s += g_hT[h * 64 + b] * __ldg(&wr[h]);
    out[b * 256 + o] = s;
}

// ---------------- launch ----------------------------------------------------
extern "C" void kernel_launch(void* const* d_in, const int* in_sizes, int n_in,
                              void* d_out, int out_size)
{
    const float* x     = (const float*)d_in[0];
    const float* W_ih0 = (const float*)d_in[1];
    const float* W_hh0 = (const float*)d_in[2];
    const float* b_ih0 = (const float*)d_in[3];
    const float* b_hh0 = (const float*)d_in[4];
    const float* W_ih1 = (const float*)d_in[5];
    const float* W_hh1 = (const float*)d_in[6];
    const float* b_ih1 = (const float*)d_in[7];
    const float* b_hh1 = (const float*)d_in[8];
    const float* W_fc  = (const float*)d_in[9];
    const float* b_fc  = (const float*)d_in[10];
    float* out = (float*)d_out;

    // layer 0 input projection: K=256, x layout
    pre_gemm_kernel<<<dim3(8, 512), 256>>>(x, W_ih0, b_ih0, b_hh0, 256, 1);
    // layer 0 recurrence (writes ys0)
    rnn_rec_kernel<<<REC_CTAS, 256>>>(W_hh0, 1);
    // layer 1 input projection: A = ys0 (internal), K=512
    pre_gemm_kernel<<<dim3(8, 512), 256>>>(x /*unused*/, W_ih1, b_ih1, b_hh1, 512, 0);
    // layer 1 recurrence (final hT only)
    rnn_rec_kernel<<<REC_CTAS, 256>>>(W_hh1, 0);
    // final FC
    fc_kernel<<<64, 256>>>(W_fc, b_fc, out);
}

// round 3
// speedup vs baseline: 1.4293x; 1.4293x over previous
#include <cuda_runtime.h>

// SmallRNNModel — 2-layer tanh RNN, B=64, T=512, I=256, H=512, O=256.
// Round 3: fused persistent kernel.
//   K1 pre_gemm:  pre0[t,b,h] = x[b,t,:]@W_ih0^T + b_ih0 + b_hh0   (GEMM 32768x512x256)
//   K2 rnn_fused: 513 iterations, per iteration 3 GEMM slices (h0@W_hh0, h0@W_ih1, h1@W_hh1)
//                 computed by 3 warp-groups; P2 forms h0[i] and h1[i-1]. 2 grid barriers/iter.
//   K3 fc:        out[b,o] = h1T(:,b)·W_fc[o,:] + b_fc[o]

#define T_STEPS 512
#define BATCH   64
#define HID     512
#define REC_CTAS 128     // 8 n-tiles x 16 k-slices
#define KSPLIT   16
#define RTHREADS 768     // 3 warp-groups x 256 threads

// ---------------- static device scratch ------------------------------------
__device__ float g_pre[T_STEPS * BATCH * HID];          // 64 MB  (layer-0 input projection)
__device__ float g_part[3 * KSPLIT * BATCH * HID];      // 6 MB   (G0 | Gp | G1 partials)
__device__ float g_h0T[HID * BATCH];                    // 128 KB (h0 transposed [h][b])
__device__ float g_h1T[HID * BATCH];                    // 128 KB
__device__ unsigned g_bar_count = 0;
__device__ volatile unsigned g_bar_gen = 0;

// ---------------- software grid barrier (all REC_CTAS co-resident) ---------
__device__ __forceinline__ void grid_barrier() {
    __syncthreads();
    if (threadIdx.x == 0) {
        __threadfence();
        unsigned gen = g_bar_gen;
        if (atomicAdd(&g_bar_count, 1u) == REC_CTAS - 1) {
            atomicExch(&g_bar_count, 0u);
            __threadfence();
            g_bar_gen = gen + 1u;
        } else {
            while (g_bar_gen == gen) { }
            __threadfence();
        }
    }
    __syncthreads();
}

// ---------------- 64x64 tile GEMM slice (K=32), 256 threads ----------------
__device__ __forceinline__ void gemm_tile(const float (*__restrict__ hs)[64],
                                          const float (*__restrict__ ws)[64],
                                          int b0, int n0, float acc[4][4]) {
    #pragma unroll
    for (int kk = 0; kk < 32; kk++) {
        float4 a = *(const float4*)&hs[kk][b0];
        float4 w = *(const float4*)&ws[kk][n0];
        float av[4] = {a.x, a.y, a.z, a.w};
        float wv[4] = {w.x, w.y, w.z, w.w};
        #pragma unroll
        for (int i = 0; i < 4; i++)
            #pragma unroll
            for (int j = 0; j < 4; j++)
                acc[i][j] += av[i] * wv[j];
    }
}

// ---------------- input-projection GEMM for layer 0 -------------------------
// g_pre[r][n] = sum_k x_row(r)[k] * W[n][k] + b1[n] + b2[n],  r = t*64 + b.
__global__ void __launch_bounds__(256)
pre_gemm_kernel(const float* __restrict__ x,
                const float* __restrict__ W,
                const float* __restrict__ b1,
                const float* __restrict__ b2)
{
    __shared__ float As[16][68];
    __shared__ float Bs[16][68];

    const int tid = threadIdx.x;
    const int nt  = blockIdx.x;        // 0..7
    const int mt  = blockIdx.y;        // 0..511  (= t)
    const int m0  = (tid >> 4) << 2;
    const int n0  = (tid & 15) << 2;

    const int lm = tid >> 2;           // 0..63
    const int lk = (tid & 3) << 2;

    const int arow = (lm * 512 + mt) * 256;   // x[b=lm][t=mt][:]
    const float* wrow = W + (nt * 64 + lm) * 256;

    float acc[4][4] = {};

    for (int k0 = 0; k0 < 256; k0 += 16) {
        float4 av = *(const float4*)(x + arow + k0 + lk);
        float4 wv = *(const float4*)(wrow + k0 + lk);
        As[lk + 0][lm] = av.x; As[lk + 1][lm] = av.y;
        As[lk + 2][lm] = av.z; As[lk + 3][lm] = av.w;
        Bs[lk + 0][lm] = wv.x; Bs[lk + 1][lm] = wv.y;
        Bs[lk + 2][lm] = wv.z; Bs[lk + 3][lm] = wv.w;
        __syncthreads();
        #pragma unroll
        for (int kk = 0; kk < 16; kk++) {
            float4 a = *(const float4*)&As[kk][m0];
            float4 w = *(const float4*)&Bs[kk][n0];
            float av4[4] = {a.x, a.y, a.z, a.w};
            float wv4[4] = {w.x, w.y, w.z, w.w};
            #pragma unroll
            for (int i = 0; i < 4; i++)
                #pragma unroll
                for (int j = 0; j < 4; j++)
                    acc[i][j] += av4[i] * wv4[j];
        }
        __syncthreads();
    }

    const int nbase = nt * 64 + n0;
    float bs[4];
    #pragma unroll
    for (int j = 0; j < 4; j++) bs[j] = b1[nbase + j] + b2[nbase + j];
    #pragma unroll
    for (int i = 0; i < 4; i++) {
        float4 o = make_float4(acc[i][0] + bs[0], acc[i][1] + bs[1],
                               acc[i][2] + bs[2], acc[i][3] + bs[3]);
        *(float4*)&g_pre[(mt * 64 + m0 + i) * 512 + nbase] = o;
    }
}

// ---------------- fused persistent two-layer recurrence ---------------------
// CTA (nt, ks): n-tile [64nt, 64nt+64), k-slice [32ks, 32ks+32).
// Warp-group 0: G0 = h0[i-1] @ W_hh0^T   (-> h0[i])
// Warp-group 1: Gp = h0[i-1] @ W_ih1^T   (-> pre1[i-1])
// Warp-group 2: G1 = h1[i-2] @ W_hh1^T   (-> h1[i-1], combined with Gp)
__global__ void __launch_bounds__(RTHREADS, 1)
rnn_fused_kernel(const float* __restrict__ W_hh0,
                 const float* __restrict__ W_ih1,
                 const float* __restrict__ W_hh1,
                 const float* __restrict__ b_ih1,
                 const float* __restrict__ b_hh1)
{
    __shared__ float W0s[32][64], Wps[32][64], W1s[32][64];
    __shared__ float h0s[32][64], h1s[32][64];

    const int tid = threadIdx.x;
    const int cta = blockIdx.x;
    const int nt  = cta & 7;
    const int ks  = cta >> 3;

    // load the three weight slices [n][k] -> smem [k][n]
    for (int e = tid; e < 2048; e += RTHREADS) {
        int n = e >> 5;
        int k = e & 31;
        int gidx = (nt * 64 + n) * 512 + ks * 32 + k;
        W0s[k][n] = W_hh0[gidx];
        Wps[k][n] = W_ih1[gidx];
        W1s[k][n] = W_hh1[gidx];
    }
    // zero initial hidden states
    {
        int g = cta * RTHREADS + tid;
        if (g < 32768) { g_h0T[g] = 0.0f; g_h1T[g] = 0.0f; }
    }
    grid_barrier();

    const int grp = tid >> 8;          // 0,1,2
    const int lt  = tid & 255;
    const int b0  = (lt >> 4) << 2;
    const int n0  = (lt & 15) << 2;
    const int g   = cta * RTHREADS + tid;        // global thread id (0..98303)

    for (int i = 0; i <= T_STEPS; i++) {
        // cooperative load of h slices (each 2048 floats = 512 float4)
        if (tid < 512)
            ((float4*)h0s)[tid] = ((const float4*)(g_h0T + ks * 2048))[tid];
        if (tid >= 256)
            ((float4*)h1s)[tid - 256] = ((const float4*)(g_h1T + ks * 2048))[tid - 256];
        __syncthreads();

        float acc[4][4] = {};
        if (grp == 0)      gemm_tile(h0s, W0s, b0, n0, acc);
        else if (grp == 1) gemm_tile(h0s, Wps, b0, n0, acc);
        else               gemm_tile(h1s, W1s, b0, n0, acc);

        float* pbuf = g_part + (grp * KSPLIT + ks) * 32768;
        #pragma unroll
        for (int r = 0; r < 4; r++) {
            float4 v = make_float4(acc[r][0], acc[r][1], acc[r][2], acc[r][3]);
            *(float4*)&pbuf[(b0 + r) * 512 + nt * 64 + n0] = v;
        }
        grid_barrier();

        // ---- P2: reduce partials, tanh, scatter to transposed h ----
        if (g < 32768) {
            // h0[i] = tanh(pre0[i] + sum_j G0_j)
            if (i < T_STEPS) {
                float s = g_pre[i * 32768 + g];
                #pragma unroll
                for (int j = 0; j < KSPLIT; j++)
                    s += g_part[j * 32768 + g];
                float v = tanhf(s);
                g_h0T[((g & 511) << 6) | (g >> 9)] = v;
            }
        } else if (g < 65536) {
            // h1[i-1] = tanh(pre1[i-1] + b_ih1 + b_hh1 + sum_j G1_j)
            if (i >= 1) {
                int idx = g - 32768;                    // = b*512 + n
                int n = idx & 511;
                float s = b_ih1[n] + b_hh1[n];
                #pragma unroll
                for (int j = 0; j < KSPLIT; j++)
                    s += g_part[(KSPLIT + j) * 32768 + idx];      // Gp (pre1)
                #pragma unroll
                for (int j = 0; j < KSPLIT; j++)
                    s += g_part[(2 * KSPLIT + j) * 32768 + idx];  // G1
                float v = tanhf(s);
                g_h1T[(n << 6) | (idx >> 9)] = v;
            }
        }
        grid_barrier();
    }
}

// ---------------- final FC ---------------------------------------------------
__global__ void __launch_bounds__(256)
fc_kernel(const float* __restrict__ Wfc, const float* __restrict__ bfc,
          float* __restrict__ out)
{
    int idx = blockIdx.x * 256 + threadIdx.x;   // 0..16383
    int o = idx >> 6;
    int b = idx & 63;
    const float* wr = Wfc + o * 512;
    float s = bfc[o];
    #pragma unroll 8
    for (int h = 0; h < 512; h++)
        s += g_h1T[h * 64 + b] * __ldg(&wr[h]);
    out[b * 256 + o] = s;
}

// ---------------- launch ------------------------------------------------------
extern "C" void kernel_launch(void* const* d_in, const int* in_sizes, int n_in,
                              void* d_out, int out_size)
{
    const float* x     = (const float*)d_in[0];
    const float* W_ih0 = (const float*)d_in[1];
    const float* W_hh0 = (const float*)d_in[2];
    const float* b_ih0 = (const float*)d_in[3];
    const float* b_hh0 = (const float*)d_in[4];
    const float* W_ih1 = (const float*)d_in[5];
    const float* W_hh1 = (const float*)d_in[6];
    const float* b_ih1 = (const float*)d_in[7];
    const float* b_hh1 = (const float*)d_in[8];
    const float* W_fc  = (const float*)d_in[9];
    const float* b_fc  = (const float*)d_in[10];
    float* out = (float*)d_out;

    pre_gemm_kernel<<<dim3(8, 512), 256>>>(x, W_ih0, b_ih0, b_hh0);
    rnn_fused_kernel<<<REC_CTAS, RTHREADS>>>(W_hh0, W_ih1, W_hh1, b_ih1, b_hh1);
    fc_kernel<<<64, 256>>>(W_fc, b_fc, out);
}

// round 5
// speedup vs baseline: 1.4745x; 1.0316x over previous
#include <cuda_runtime.h>
#include <cstdint>

// SmallRNNModel — 2-layer tanh RNN, B=64, T=512, I=256, H=512, O=256.
// Round 5: flat 128-CTA persistent fused kernel (no clusters — R4 deadlocked on
// cluster placement limits), coalesced [n][b] layouts, f32x2 FFMA with
// pre-duplicated weight pairs in smem, 2 grid barriers/iter.

#define T_STEPS 512
#define HID     512
#define BATCH   64
#define NCTA    128      // 16 k-slices x 8 n-tiles, flat launch
#define KSPLIT  16
#define RTHREADS 768     // 3 GEMM groups x 256
#define NB      32768    // HID*BATCH

// ---------------- static device scratch ------------------------------------
__device__ float g_pre[T_STEPS * NB];          // [t][n][b]  64 MB
__device__ float g_part[3 * KSPLIT * NB];      // [grp*16+ks][n][b]  6 MB
__device__ float g_h0T[NB];                    // [n][b]
__device__ float g_h1T[NB];                    // [n][b]
__device__ unsigned g_bar_count = 0;
__device__ volatile unsigned g_bar_gen = 0;

// ---------------- f32x2 helpers (bit-exact fp32, 2x FFMA throughput) -------
__device__ __forceinline__ uint64_t pk2(float x, float y) {
    uint64_t r; asm("mov.b64 %0,{%1,%2};" : "=l"(r) : "f"(x), "f"(y)); return r;
}
__device__ __forceinline__ void upk2(uint64_t v, float& x, float& y) {
    asm("mov.b64 {%0,%1},%2;" : "=f"(x), "=f"(y) : "l"(v));
}
__device__ __forceinline__ uint64_t fma2(uint64_t a, uint64_t b, uint64_t c) {
    uint64_t d; asm("fma.rn.f32x2 %0,%1,%2,%3;" : "=l"(d) : "l"(a), "l"(b), "l"(c));
    return d;
}

// ---------------- software grid barrier (128 flat CTAs, 1 per SM) ----------
__device__ __forceinline__ void grid_barrier() {
    __syncthreads();
    if (threadIdx.x == 0) {
        __threadfence();
        unsigned gen = g_bar_gen;
        if (atomicAdd(&g_bar_count, 1u) == NCTA - 1) {
            atomicExch(&g_bar_count, 0u);
            __threadfence();
            g_bar_gen = gen + 1u;
        } else {
            while (g_bar_gen == gen) { }
            __threadfence();
        }
    }
    __syncthreads();
}

// ---------------- input-projection GEMM (layer 0) ---------------------------
// g_pre[t][n][b] = sum_k x[b][t][k]*W_ih0[n][k] + b_ih0[n] + b_hh0[n]
__global__ void __launch_bounds__(256)
pre_gemm_kernel(const float* __restrict__ x,
                const float* __restrict__ W,
                const float* __restrict__ b1,
                const float* __restrict__ b2)
{
    __shared__ float As[16][68];   // [k][b]
    __shared__ float Bs[16][68];   // [k][n]

    const int tid = threadIdx.x;
    const int nt  = blockIdx.x;        // 0..7
    const int mt  = blockIdx.y;        // 0..511 (= t)
    const int n0  = (tid >> 4) << 2;
    const int m0  = (tid & 15) << 2;

    const int lm = tid >> 2;           // 0..63
    const int lk = (tid & 3) << 2;

    const int arow = (lm * 512 + mt) * 256;          // x[b=lm][t=mt][:]
    const float* wrow = W + (nt * 64 + lm) * 256;

    uint64_t acc[4][2] = {};           // [b-row][n-pair]

    for (int k0 = 0; k0 < 256; k0 += 16) {
        float4 av = *(const float4*)(x + arow + k0 + lk);
        float4 wv = *(const float4*)(wrow + k0 + lk);
        As[lk + 0][lm] = av.x; As[lk + 1][lm] = av.y;
        As[lk + 2][lm] = av.z; As[lk + 3][lm] = av.w;
        Bs[lk + 0][lm] = wv.x; Bs[lk + 1][lm] = wv.y;
        Bs[lk + 2][lm] = wv.z; Bs[lk + 3][lm] = wv.w;
        __syncthreads();
        #pragma unroll
        for (int kk = 0; kk < 16; kk++) {
            float4 a = *(const float4*)&As[kk][m0];
            float4 w = *(const float4*)&Bs[kk][n0];
            uint64_t w01 = pk2(w.x, w.y), w23 = pk2(w.z, w.w);
            float am[4] = {a.x, a.y, a.z, a.w};
            #pragma unroll
            for (int i = 0; i < 4; i++) {
                uint64_t aa = pk2(am[i], am[i]);
                acc[i][0] = fma2(aa, w01, acc[i][0]);
                acc[i][1] = fma2(aa, w23, acc[i][1]);
            }
        }
        __syncthreads();
    }

    float av[4][4];
    #pragma unroll
    for (int i = 0; i < 4; i++) {
        upk2(acc[i][0], av[i][0], av[i][1]);
        upk2(acc[i][1], av[i][2], av[i][3]);
    }
    const int nbase = nt * 64 + n0;
    #pragma unroll
    for (int c = 0; c < 4; c++) {
        float bs = b1[nbase + c] + b2[nbase + c];
        float4 o = make_float4(av[0][c] + bs, av[1][c] + bs,
                               av[2][c] + bs, av[3][c] + bs);
        *(float4*)&g_pre[mt * NB + (nbase + c) * 64 + m0] = o;   // [t][n][b]
    }
}

// ---------------- fused persistent two-layer recurrence ---------------------
// CTA (nt, ks): n-tile [64nt,64nt+64), k-slice [32ks,32ks+32).
// GEMM groups (256 thr each): 0: h0@W_hh0 -> G0; 1: h0@W_ih1 -> Gp; 2: h1@W_hh1 -> G1.
// P2 roles: tid<256 h0-reduce; 256..511 Gp-reduce+final h1; 512..767 G1-reduce.
__global__ void __launch_bounds__(RTHREADS, 1)
rnn_fused_kernel(const float* __restrict__ W_hh0,
                 const float* __restrict__ W_ih1,
                 const float* __restrict__ W_hh1,
                 const float* __restrict__ b_ih1,
                 const float* __restrict__ b_hh1)
{
    // weights stored as duplicated pairs {w,w} so inner loop is LDS+FFMA2 only
    __shared__ float2 W0d[32][64], Wpd[32][64], W1d[32][64];   // 48 KB
    __shared__ float h0s[32][64], h1s[32][64];                 // 16 KB
    __shared__ float red1[256];

    const int tid = threadIdx.x;
    const int cta = blockIdx.x;
    const int nt  = cta & 7;
    const int ks  = cta >> 3;

    // load weight slices: n in [64nt,64nt+64), k in [32ks,32ks+32)
    for (int e = tid; e < 2048; e += RTHREADS) {
        int n = e >> 5, k = e & 31;
        int gidx = (nt * 64 + n) * 512 + ks * 32 + k;
        float w0 = W_hh0[gidx], wp = W_ih1[gidx], w1 = W_hh1[gidx];
        W0d[k][n] = make_float2(w0, w0);
        Wpd[k][n] = make_float2(wp, wp);
        W1d[k][n] = make_float2(w1, w1);
    }
    // zero initial hidden states
    {
        int g = cta * RTHREADS + tid;
        if (g < NB) { g_h0T[g] = 0.0f; g_h1T[g] = 0.0f; }
    }

    // ---- P2 constants ----
    const int rlt   = tid & 255;
    const int n_off = rlt >> 6;
    const int rb    = rlt & 63;
    const int rn    = ks * 32 + nt * 4 + n_off;      // this thread's global n
    const float bias1 = b_ih1[rn] + b_hh1[rn];

    // ---- GEMM constants ----
    const int grp = tid >> 8;                 // 0,1,2
    const int lt  = tid & 255;
    const int n0  = (lt >> 4) << 2;           // 4 n per thread
    const int b0  = (lt & 15) << 2;           // 4 b per thread
    const float (*hs)[64] = (grp == 2) ? h1s : h0s;
    const float2 (*wd)[64] = (grp == 0) ? W0d : (grp == 1) ? Wpd : W1d;
    const int pofs = ((grp * KSPLIT + ks) * 512 + nt * 64 + n0) * 64 + b0;

    grid_barrier();

    for (int i = 0; i <= T_STEPS; i++) {
        // ---- copy h slices (rows [32ks,32ks+32) of [n][b]) into smem ----
        if (tid < 512)
            ((float4*)h0s)[tid] = ((const float4*)(g_h0T + ks * 2048))[tid];
        if (tid >= 256)
            ((float4*)h1s)[tid - 256] = ((const float4*)(g_h1T + ks * 2048))[tid - 256];
        __syncthreads();

        // ---- GEMM slice: 4b x 4n x K=32, f32x2 over the b-pairs ----
        uint64_t acc[2][4] = {};
        #pragma unroll
        for (int kk = 0; kk < 32; kk++) {
            ulonglong2 ap = *(const ulonglong2*)&hs[kk][b0];      // {b0,b0+1},{b0+2,b0+3}
            ulonglong2 wA = *(const ulonglong2*)&wd[kk][n0];      // dup pairs n0,n0+1
            ulonglong2 wB = *(const ulonglong2*)&wd[kk][n0 + 2];  // dup pairs n0+2,n0+3
            acc[0][0] = fma2(ap.x, wA.x, acc[0][0]);
            acc[0][1] = fma2(ap.x, wA.y, acc[0][1]);
            acc[0][2] = fma2(ap.x, wB.x, acc[0][2]);
            acc[0][3] = fma2(ap.x, wB.y, acc[0][3]);
            acc[1][0] = fma2(ap.y, wA.x, acc[1][0]);
            acc[1][1] = fma2(ap.y, wA.y, acc[1][1]);
            acc[1][2] = fma2(ap.y, wB.x, acc[1][2]);
            acc[1][3] = fma2(ap.y, wB.y, acc[1][3]);
        }
        // store partials to [grp*16+ks][n][b] (coalesced: warp spans b)
        #pragma unroll
        for (int c = 0; c < 4; c++) {
            float x0, x1, x2, x3;
            upk2(acc[0][c], x0, x1);
            upk2(acc[1][c], x2, x3);
            *(float4*)&g_part[pofs + c * 64] = make_float4(x0, x1, x2, x3);
        }

        grid_barrier();

        // ---- P2: coalesced reduce + tanh -> h buffers ----
        if (tid < 256) {
            if (i < T_STEPS) {
                float s = g_pre[i * NB + rn * 64 + rb];
                #pragma unroll
                for (int j = 0; j < KSPLIT; j++)
                    s += g_part[(j * 512 + rn) * 64 + rb];               // G0
                g_h0T[rn * 64 + rb] = tanhf(s);
            }
        } else if (tid >= 512) {
            if (i >= 1) {
                float s = 0.0f;
                #pragma unroll
                for (int j = 0; j < KSPLIT; j++)
                    s += g_part[((2 * KSPLIT + j) * 512 + rn) * 64 + rb]; // G1
                red1[rlt] = s;
            }
        }
        float gp = 0.0f;
        if (tid >= 256 && tid < 512 && i >= 1) {
            gp = bias1;
            #pragma unroll
            for (int j = 0; j < KSPLIT; j++)
                gp += g_part[((KSPLIT + j) * 512 + rn) * 64 + rb];        // Gp
        }
        __syncthreads();
        if (tid >= 256 && tid < 512 && i >= 1)
            g_h1T[rn * 64 + rb] = tanhf(gp + red1[rlt]);

        grid_barrier();
    }
}

// ---------------- final FC ---------------------------------------------------
__global__ void __launch_bounds__(256)
fc_kernel(const float* __restrict__ Wfc, const float* __restrict__ bfc,
          float* __restrict__ out)
{
    int idx = blockIdx.x * 256 + threadIdx.x;   // 0..16383
    int o = idx >> 6;
    int b = idx & 63;
    const float* wr = Wfc + o * 512;
    float s = bfc[o];
    #pragma unroll 8
    for (int h = 0; h < 512; h++)
        s += g_h1T[h * 64 + b] * __ldg(&wr[h]);
    out[b * 256 + o] = s;
}

// ---------------- launch ------------------------------------------------------
extern "C" void kernel_launch(void* const* d_in, const int* in_sizes, int n_in,
                              void* d_out, int out_size)
{
    const float* x     = (const float*)d_in[0];
    const float* W_ih0 = (const float*)d_in[1];
    const float* W_hh0 = (const float*)d_in[2];
    const float* b_ih0 = (const float*)d_in[3];
    const float* b_hh0 = (const float*)d_in[4];
    const float* W_ih1 = (const float*)d_in[5];
    const float* W_hh1 = (const float*)d_in[6];
    const float* b_ih1 = (const float*)d_in[7];
    const float* b_hh1 = (const float*)d_in[8];
    const float* W_fc  = (const float*)d_in[9];
    const float* b_fc  = (const float*)d_in[10];
    float* out = (float*)d_out;

    pre_gemm_kernel<<<dim3(8, 512), 256>>>(x, W_ih0, b_ih0, b_hh0);
    rnn_fused_kernel<<<NCTA, RTHREADS>>>(W_hh0, W_ih1, W_hh1, b_ih1, b_hh1);
    fc_kernel<<<64, 256>>>(W_fc, b_fc, out);
}